// round 1
// baseline (speedup 1.0000x reference)
#include <cuda_runtime.h>
#include <stdint.h>
#include <math.h>

#define D        27
#define QB       512     // query batch
#define NCLS     11
#define KNN      3
#define NBLK     444     // main-kernel blocks (148 SMs * 3)
#define TILE     128     // train points staged per smem tile
#define MTHREADS 128     // main kernel threads (4 queries/thread)
#define QPT      4

// ---------------- static device scratch (no allocations allowed) ----------
__device__ unsigned int g_scale_bits[D];
__device__ float        g_inv[D];
__device__ float        g_qm[QB * D];   // -2 * scaled query, [QB][D]
__device__ float        g_qn[QB];       // ||q_s||^2 per query
__device__ float2       g_part[(size_t)QB * NBLK * KNN]; // {d2', idx-bits}

// ---------------- f32x2 helpers -------------------------------------------
__device__ __forceinline__ unsigned long long pack2(float a, float b) {
    unsigned long long r;
    asm("mov.b64 %0, {%1, %2};"
        : "=l"(r) : "r"(__float_as_uint(a)), "r"(__float_as_uint(b)));
    return r;
}
__device__ __forceinline__ void unpack2(unsigned long long v, float& a, float& b) {
    unsigned int x, y;
    asm("mov.b64 {%0, %1}, %2;" : "=r"(x), "=r"(y) : "l"(v));
    a = __uint_as_float(x);
    b = __uint_as_float(y);
}
__device__ __forceinline__ void fma2(unsigned long long& acc,
                                     unsigned long long a, unsigned long long b) {
    asm("fma.rn.f32x2 %0, %1, %2, %0;" : "+l"(acc) : "l"(a), "l"(b));
}

// ---------------- kernel 1: zero the scale accumulators -------------------
__global__ void k_init() {
    if (threadIdx.x < D) g_scale_bits[threadIdx.x] = 0u;
}

// ---------------- kernel 2: per-column max|x| over train ------------------
// blockDim.x = 216 (= 8*27) so each thread's column index is loop-invariant
// and global loads stay fully coalesced.
__global__ void k_scale(const float* __restrict__ tf, int n) {
    __shared__ unsigned int sm[D];
    if (threadIdx.x < D) sm[threadIdx.x] = 0u;
    __syncthreads();
    int i = blockIdx.x * blockDim.x + threadIdx.x;
    int col = i % D;
    int stride = gridDim.x * blockDim.x;   // multiple of 27
    float m = 0.f;
    for (; i < n; i += stride) m = fmaxf(m, fabsf(tf[i]));
    atomicMax(&sm[col], __float_as_uint(m));   // m >= 0 -> uint order == float order
    __syncthreads();
    if (threadIdx.x < D) atomicMax(&g_scale_bits[threadIdx.x], sm[threadIdx.x]);
}

// ---------------- kernel 3: inv scale + scaled queries --------------------
__global__ void k_query(const float* __restrict__ q) {
    __shared__ float inv[D];
    int t = threadIdx.x;
    if (t < D) {
        float s = __uint_as_float(g_scale_bits[t]);
        float v = (s != 0.f) ? (1.f / s) : 0.f;   // divide_no_nan
        inv[t] = v;
        g_inv[t] = v;
    }
    __syncthreads();
    // one query per thread (blockDim == QB)
    float qn = 0.f;
    #pragma unroll
    for (int d = 0; d < D; ++d) {
        float v = q[t * D + d] * inv[d];
        qn = fmaf(v, v, qn);
        g_qm[t * D + d] = -2.f * v;
    }
    g_qn[t] = qn;
}

// ---------------- kernel 4: main distance + per-block top-3 ---------------
__global__ void __launch_bounds__(MTHREADS, 2)
k_main(const float* __restrict__ tf, int N) {
    __shared__ float s_tile[TILE * 28];    // 27 scaled features + xn per point
    __shared__ float s_inv[D];
    const int tid = threadIdx.x;
    const int bid = blockIdx.x;
    if (tid < D) s_inv[tid] = g_inv[tid];

    // register-resident packed queries: thread owns q = tid, tid+128, tid+256, tid+384
    unsigned long long q01[D], q23[D];
    #pragma unroll
    for (int d = 0; d < D; ++d) {
        float a = g_qm[(tid          ) * D + d];
        float b = g_qm[(tid + 128    ) * D + d];
        float c = g_qm[(tid + 256    ) * D + d];
        float e = g_qm[(tid + 384    ) * D + d];
        q01[d] = pack2(a, b);
        q23[d] = pack2(c, e);
    }

    const float INF = __int_as_float(0x7f800000);
    float t0[QPT], t1[QPT], t2[QPT];
    int   i0[QPT], i1[QPT], i2[QPT];
    #pragma unroll
    for (int k = 0; k < QPT; ++k) {
        t0[k] = t1[k] = t2[k] = INF;
        i0[k] = i1[k] = i2[k] = 0;
    }

    const int chunk = (N + NBLK - 1) / NBLK;
    const int base  = bid * chunk;
    const int end   = (base + chunk < N) ? (base + chunk) : N;

    for (int pt = base; pt < end; pt += TILE) {
        const int tn = (end - pt < TILE) ? (end - pt) : TILE;
        __syncthreads();   // protect s_tile reuse (also orders s_inv on iter 0)
        // stage + scale the train tile (coalesced)
        for (int f = tid; f < tn * D; f += MTHREADS) {
            int i = f / D;
            int d = f - i * D;
            s_tile[i * 28 + d] = tf[(pt + i) * D + d] * s_inv[d];
        }
        __syncthreads();
        // per-point squared norm xn
        for (int i = tid; i < tn; i += MTHREADS) {
            float s = 0.f;
            #pragma unroll
            for (int d = 0; d < D; ++d) {
                float v = s_tile[i * 28 + d];
                s = fmaf(v, v, s);
            }
            s_tile[i * 28 + 27] = s;
        }
        __syncthreads();

        // process: d2' = xn - 2 * q.x  (qn added at the end; ordering-invariant)
        for (int i = 0; i < tn; ++i) {
            const float4* xp = (const float4*)(s_tile + i * 28);
            float xv[28];
            #pragma unroll
            for (int j = 0; j < 7; ++j) {     // broadcast LDS.128
                float4 v = xp[j];
                xv[4*j+0] = v.x; xv[4*j+1] = v.y; xv[4*j+2] = v.z; xv[4*j+3] = v.w;
            }
            unsigned long long a01 = pack2(xv[27], xv[27]);  // acc starts at {xn,xn}
            unsigned long long a23 = a01;
            #pragma unroll
            for (int d = 0; d < D; ++d) {
                unsigned long long x2 = pack2(xv[d], xv[d]);
                fma2(a01, x2, q01[d]);
                fma2(a23, x2, q23[d]);
            }
            float d2[QPT];
            unpack2(a01, d2[0], d2[1]);
            unpack2(a23, d2[2], d2[3]);
            const int idx = pt + i;
            #pragma unroll
            for (int k = 0; k < QPT; ++k) {
                float v = d2[k];
                if (v < t2[k]) {
                    if (v < t1[k]) {
                        t2[k] = t1[k]; i2[k] = i1[k];
                        if (v < t0[k]) { t1[k] = t0[k]; i1[k] = i0[k]; t0[k] = v; i0[k] = idx; }
                        else           { t1[k] = v;     i1[k] = idx; }
                    } else { t2[k] = v; i2[k] = idx; }
                }
            }
        }
    }

    // per-thread top-3 IS the per-(query,block) top-3 — write directly
    #pragma unroll
    for (int k = 0; k < QPT; ++k) {
        int q = tid + k * MTHREADS;
        float2* o = g_part + ((size_t)q * NBLK + bid) * KNN;
        o[0] = make_float2(t0[k], __int_as_float(i0[k]));
        o[1] = make_float2(t1[k], __int_as_float(i1[k]));
        o[2] = make_float2(t2[k], __int_as_float(i2[k]));
    }
}

// ---------------- kernel 5: merge partials, kd + vote ---------------------
__global__ void k_reduce(const float* __restrict__ labels, float* __restrict__ out) {
    const int q   = blockIdx.x;
    const int tid = threadIdx.x;   // 128
    __shared__ float sd[3 * 128];
    __shared__ int   si[3 * 128];
    const float INF = __int_as_float(0x7f800000);

    float b0 = INF, b1 = INF, b2 = INF;
    int   x0 = 0,   x1 = 0,   x2 = 0;
    const float2* p = g_part + (size_t)q * NBLK * KNN;
    for (int e = tid; e < NBLK * KNN; e += 128) {
        float2 v = p[e];
        float d = v.x; int ix = __float_as_int(v.y);
        if (d < b2) {
            if (d < b1) {
                b2 = b1; x2 = x1;
                if (d < b0) { b1 = b0; x1 = x0; b0 = d; x0 = ix; }
                else        { b1 = d;  x1 = ix; }
            } else { b2 = d; x2 = ix; }
        }
    }
    sd[tid      ] = b0; si[tid      ] = x0;
    sd[tid + 128] = b1; si[tid + 128] = x1;
    sd[tid + 256] = b2; si[tid + 256] = x2;
    __syncthreads();

    if (tid == 0) {
        float r0 = INF, r1 = INF, r2 = INF;
        int   y0 = 0,   y1 = 0,   y2 = 0;
        for (int e = 0; e < 3 * 128; ++e) {
            float d = sd[e]; int ix = si[e];
            if (d < r2 || (d == r2 && ix < y2)) {
                if (d < r1 || (d == r1 && ix < y1)) {
                    r2 = r1; y2 = y1;
                    if (d < r0 || (d == r0 && ix < y0)) { r1 = r0; y1 = y0; r0 = d; y0 = ix; }
                    else                                 { r1 = d;  y1 = ix; }
                } else { r2 = d; y2 = ix; }
            }
        }
        const float qn = g_qn[q];
        const float kd0 = sqrtf(fmaxf(r0 + qn, 0.f));
        const float kd1 = sqrtf(fmaxf(r1 + qn, 0.f));
        const float kd2 = sqrtf(fmaxf(r2 + qn, 0.f));
        out[q * KNN + 0] = kd0;
        out[q * KNN + 1] = kd1;
        out[q * KNN + 2] = kd2;

        const float w0 = (kd0 == 0.f) ? 1.f : kd0;
        const float w1 = (kd1 == 0.f) ? 1.f : kd1;
        const float w2 = (kd2 == 0.f) ? 1.f : kd2;
        const float* l0 = labels + (size_t)y0 * NCLS;
        const float* l1 = labels + (size_t)y1 * NCLS;
        const float* l2 = labels + (size_t)y2 * NCLS;

        float votes[NCLS];
        #pragma unroll
        for (int c = 0; c < NCLS; ++c)
            votes[c] = l0[c] / w0 + l1[c] / w1 + l2[c] / w2;

        int am = 0; float bm = votes[0];
        #pragma unroll
        for (int c = 1; c < NCLS; ++c)
            if (votes[c] > bm) { bm = votes[c]; am = c; }

        const bool zero_hit = (kd0 == 0.f);
        float* ro = out + QB * KNN + q * NCLS;
        #pragma unroll
        for (int c = 0; c < NCLS; ++c)
            ro[c] = zero_hit ? l0[c] : ((c == am) ? 1.f : 0.f);
    }
}

// ---------------- launch ---------------------------------------------------
extern "C" void kernel_launch(void* const* d_in, const int* in_sizes, int n_in,
                              void* d_out, int out_size) {
    const float* query = (const float*)d_in[0];   // [512,27]
    const float* tf    = (const float*)d_in[1];   // [N,27]
    const float* tl    = (const float*)d_in[2];   // [N,11]
    float* out = (float*)d_out;                   // [512*3] kd ++ [512*11] result
    const int n_elems = in_sizes[1];
    const int N = n_elems / D;

    k_init  <<<1,   32 >>>();
    k_scale <<<512, 216>>>(tf, n_elems);
    k_query <<<1,   QB >>>(query);
    k_main  <<<NBLK, MTHREADS>>>(tf, N);
    k_reduce<<<QB,  128>>>(tl, out);
}